// round 2
// baseline (speedup 1.0000x reference)
#include <cuda_runtime.h>
#include <math_constants.h>

#define B_ 256
#define P_ 196
#define E_ 2048
#define D_ 512
#define A_ 512
#define M_ (B_*P_)   // 50176

// Scratch (no allocations allowed): att2 [B,A], att logits [B,P]
__device__ float g_att2[B_*A_];
__device__ float g_att[M_];

// ---------------------------------------------------------------------------
// Stage 0: zero the logit accumulator (main GEMM epilogue uses atomicAdd)
// ---------------------------------------------------------------------------
__global__ void init_att_kernel() {
    int i = blockIdx.x * blockDim.x + threadIdx.x;
    if (i < M_) g_att[i] = 0.0f;
}

// ---------------------------------------------------------------------------
// Stage 1: att2[b,a] = decoder_hidden[b,:] @ W_dec[:,a] + b_dec[a]
// grid (A/128, B/16), 256 threads. Each thread: 1 column x 8 batches.
// ---------------------------------------------------------------------------
__global__ void att2_kernel(const float* __restrict__ dh,
                            const float* __restrict__ Wdec,
                            const float* __restrict__ bdec) {
    __shared__ float sdh[16][D_];   // 32 KB
    const int colBase = blockIdx.x * 128;
    const int bBase   = blockIdx.y * 16;
    const int t = threadIdx.x;

    for (int i = t; i < 16 * D_; i += 256) {
        int bb = i / D_, k = i % D_;
        sdh[bb][k] = dh[(bBase + bb) * D_ + k];
    }
    __syncthreads();

    const int col   = colBase + (t & 127);
    const int bhalf = t >> 7;            // 0 or 1 -> batches bhalf*8..+8
    float acc[8];
    #pragma unroll
    for (int i = 0; i < 8; i++) acc[i] = 0.0f;

    for (int k = 0; k < D_; k++) {
        float w = Wdec[k * A_ + col];
        #pragma unroll
        for (int i = 0; i < 8; i++)
            acc[i] = fmaf(sdh[bhalf * 8 + i][k], w, acc[i]);
    }
    float bd = bdec[col];
    #pragma unroll
    for (int i = 0; i < 8; i++)
        g_att2[(bBase + bhalf * 8 + i) * A_ + col] = acc[i] + bd;
}

// ---------------------------------------------------------------------------
// Stage 2: main fused GEMM + epilogue.
//   att1 = enc[M,E] @ Wenc[E,A]           (tiled SGEMM, BM=128 BN=128 BK=8)
//   att[r] += sum_col relu(att1 + b_enc[col] + att2[b,col]) * w_full[col]
// b_full is softmax-invariant and dropped.
// ---------------------------------------------------------------------------
#define BM 128
#define BN 128
#define BK 8
#define TM 8
#define TN 8

__global__ __launch_bounds__(256, 2)
void main_gemm_kernel(const float* __restrict__ enc,
                      const float* __restrict__ Wenc,
                      const float* __restrict__ benc,
                      const float* __restrict__ wfull) {
    __shared__ float As[BK][BM];
    __shared__ float Bs[BK][BN];
    __shared__ float red[BM][17];   // padded to break bank conflicts

    const int t  = threadIdx.x;
    const int tx = t & 15;          // 0..15 (col groups)
    const int ty = t >> 4;          // 0..15 (row groups)
    const int rowBase = blockIdx.x * BM;
    const int colBase = blockIdx.y * BN;

    // loader mapping
    const int aRow = t >> 1;          // 0..127
    const int aK   = (t & 1) * 4;     // 0 or 4
    const int bK   = t >> 5;          // 0..7
    const int bN   = (t & 31) * 4;    // 0..124

    float acc[TM][TN] = {};

    const float* aPtr = enc + (size_t)(rowBase + aRow) * E_ + aK;
    const float* bPtr = Wenc + (size_t)bK * A_ + colBase + bN;

    for (int k0 = 0; k0 < E_; k0 += BK) {
        float4 av = *(const float4*)(aPtr + k0);
        As[aK + 0][aRow] = av.x;
        As[aK + 1][aRow] = av.y;
        As[aK + 2][aRow] = av.z;
        As[aK + 3][aRow] = av.w;
        float4 bv = *(const float4*)(bPtr + (size_t)k0 * A_);
        *(float4*)&Bs[bK][bN] = bv;
        __syncthreads();

        #pragma unroll
        for (int kk = 0; kk < BK; kk++) {
            float4 a0 = *(const float4*)&As[kk][ty * TM];
            float4 a1 = *(const float4*)&As[kk][ty * TM + 4];
            float4 b0 = *(const float4*)&Bs[kk][tx * TN];
            float4 b1 = *(const float4*)&Bs[kk][tx * TN + 4];
            float a[TM] = {a0.x, a0.y, a0.z, a0.w, a1.x, a1.y, a1.z, a1.w};
            float b[TN] = {b0.x, b0.y, b0.z, b0.w, b1.x, b1.y, b1.z, b1.w};
            #pragma unroll
            for (int i = 0; i < TM; i++)
                #pragma unroll
                for (int j = 0; j < TN; j++)
                    acc[i][j] = fmaf(a[i], b[j], acc[i][j]);
        }
        __syncthreads();
    }

    // epilogue: bias + att2 + relu, project onto w_full, reduce per row
    float w[TN], be[TN];
    #pragma unroll
    for (int j = 0; j < TN; j++) {
        int c = colBase + tx * TN + j;
        w[j]  = wfull[c];
        be[j] = benc[c];
    }
    #pragma unroll
    for (int i = 0; i < TM; i++) {
        int r    = rowBase + ty * TM + i;
        int bidx = r / P_;
        const float* a2 = g_att2 + (size_t)bidx * A_ + colBase + tx * TN;
        float part = 0.0f;
        #pragma unroll
        for (int j = 0; j < TN; j++) {
            float v = acc[i][j] + be[j] + a2[j];
            v = fmaxf(v, 0.0f);
            part = fmaf(v, w[j], part);
        }
        red[ty * TM + i][tx] = part;
    }
    __syncthreads();
    if (t < BM) {
        float s = 0.0f;
        #pragma unroll
        for (int j = 0; j < 16; j++) s += red[t][j];
        atomicAdd(&g_att[rowBase + t], s);
    }
}

// ---------------------------------------------------------------------------
// Stage 3: softmax over P=196 per batch. alpha written directly to output.
// ---------------------------------------------------------------------------
__global__ void softmax_kernel(float* __restrict__ alpha_out) {
    __shared__ float sdata[256];
    const int b = blockIdx.x;
    const int t = threadIdx.x;

    float v = (t < P_) ? g_att[b * P_ + t] : -CUDART_INF_F;
    sdata[t] = v;
    __syncthreads();
    for (int s = 128; s > 0; s >>= 1) {
        if (t < s) sdata[t] = fmaxf(sdata[t], sdata[t + s]);
        __syncthreads();
    }
    float m = sdata[0];
    __syncthreads();

    float e = (t < P_) ? expf(v - m) : 0.0f;
    sdata[t] = e;
    __syncthreads();
    for (int s = 128; s > 0; s >>= 1) {
        if (t < s) sdata[t] += sdata[t + s];
        __syncthreads();
    }
    float inv = 1.0f / sdata[0];
    if (t < P_) alpha_out[b * P_ + t] = e * inv;
}

// ---------------------------------------------------------------------------
// Stage 4: awe[b,e] = sum_p enc[b,p,e] * alpha[b,p]   (HBM-bound, 411 MB)
// grid (E/256, B), 256 threads
// ---------------------------------------------------------------------------
__global__ void awe_kernel(const float* __restrict__ enc,
                           const float* __restrict__ alpha,
                           float* __restrict__ awe) {
    __shared__ float sa[P_];
    const int b = blockIdx.y;
    const int e = blockIdx.x * 256 + threadIdx.x;
    for (int i = threadIdx.x; i < P_; i += 256)
        sa[i] = alpha[b * P_ + i];
    __syncthreads();

    const float* base = enc + (size_t)b * P_ * E_ + e;
    float acc = 0.0f;
    #pragma unroll 4
    for (int p = 0; p < P_; p++)
        acc = fmaf(base[(size_t)p * E_], sa[p], acc);
    awe[b * E_ + e] = acc;
}

// ---------------------------------------------------------------------------
extern "C" void kernel_launch(void* const* d_in, const int* in_sizes, int n_in,
                              void* d_out, int out_size) {
    const float* enc   = (const float*)d_in[0];  // [B,P,E]
    const float* dh    = (const float*)d_in[1];  // [B,D]
    const float* Wenc  = (const float*)d_in[2];  // [E,A]
    const float* benc  = (const float*)d_in[3];  // [A]
    const float* Wdec  = (const float*)d_in[4];  // [D,A]
    const float* bdec  = (const float*)d_in[5];  // [A]
    const float* wfull = (const float*)d_in[6];  // [A,1]
    // d_in[7] = b_full: softmax-invariant, unused.

    float* awe   = (float*)d_out;                // [B,E] first
    float* alpha = (float*)d_out + (size_t)B_ * E_;  // [B,P] second

    init_att_kernel<<<(M_ + 255) / 256, 256>>>();
    att2_kernel<<<dim3(A_ / 128, B_ / 16), 256>>>(dh, Wdec, bdec);
    main_gemm_kernel<<<dim3(M_ / BM, A_ / BN), 256>>>(enc, Wenc, benc, wfull);
    softmax_kernel<<<B_, 256>>>(alpha);
    awe_kernel<<<dim3(E_ / 256, B_), 256>>>(enc, alpha, awe);
}

// round 3
// speedup vs baseline: 3.0087x; 3.0087x over previous
#include <cuda_runtime.h>
#include <math_constants.h>
#include <cstdint>

#define B_ 256
#define P_ 196
#define E_ 2048
#define D_ 512
#define A_ 512
#define M_ (B_*P_)   // 50176

// Scratch: att2 [B,A], att logits [B,P]
__device__ float g_att2[B_*A_];
__device__ float g_att[M_];

// ---------------------------------------------------------------------------
__global__ void init_att_kernel() {
    int i = blockIdx.x * blockDim.x + threadIdx.x;
    if (i < M_) g_att[i] = 0.0f;
}

// ---------------------------------------------------------------------------
// Stage 1: att2[b,a] = decoder_hidden[b,:] @ W_dec[:,a] + b_dec[a]
// ---------------------------------------------------------------------------
__global__ void att2_kernel(const float* __restrict__ dh,
                            const float* __restrict__ Wdec,
                            const float* __restrict__ bdec) {
    __shared__ float sdh[16][D_];
    const int colBase = blockIdx.x * 128;
    const int bBase   = blockIdx.y * 16;
    const int t = threadIdx.x;

    for (int i = t; i < 16 * D_; i += 256) {
        int bb = i / D_, k = i % D_;
        sdh[bb][k] = dh[(bBase + bb) * D_ + k];
    }
    __syncthreads();

    const int col   = colBase + (t & 127);
    const int bhalf = t >> 7;
    float acc[8];
    #pragma unroll
    for (int i = 0; i < 8; i++) acc[i] = 0.0f;

    for (int k = 0; k < D_; k++) {
        float w = Wdec[k * A_ + col];
        #pragma unroll
        for (int i = 0; i < 8; i++)
            acc[i] = fmaf(sdh[bhalf * 8 + i][k], w, acc[i]);
    }
    float bd = bdec[col];
    #pragma unroll
    for (int i = 0; i < 8; i++)
        g_att2[(bBase + bhalf * 8 + i) * A_ + col] = acc[i] + bd;
}

// ---------------------------------------------------------------------------
// Stage 2: tf32 tensor-core GEMM + fused epilogue.
//   att1 = enc[M,E] @ Wenc[E,A]   then   att[r] += sum_c relu(att1+benc+att2)*w
// BM=128, BN=256, BK=32, 256 threads (8 warps, warp tile 64x64, m16n8k8 tf32)
// ---------------------------------------------------------------------------
#define BM 128
#define BN 256
#define BK 32
#define KTILES (E_/BK)       // 64
#define AS_STRIDE 36         // floats per A row (pad 4): banks (4m+k) conflict-free
#define BS_STRIDE 264        // floats per B row (pad 8): banks (8k+n) conflict-free
#define AS_FLOATS (BM*AS_STRIDE)     // 4608
#define BS_FLOATS (BK*BS_STRIDE)     // 8448
#define SMEM_FLOATS (2*AS_FLOATS + 2*BS_FLOATS)   // 26112 floats = 104448 B

__device__ __forceinline__ void cp16(uint32_t saddr, const void* gaddr) {
    asm volatile("cp.async.cg.shared.global [%0], [%1], 16;\n"
                 :: "r"(saddr), "l"(gaddr));
}

#define MMA_TF32(d, a, b)                                              \
    asm volatile(                                                      \
        "mma.sync.aligned.m16n8k8.row.col.f32.tf32.tf32.f32 "          \
        "{%0,%1,%2,%3}, {%4,%5,%6,%7}, {%8,%9}, {%0,%1,%2,%3};\n"      \
        : "+f"((d)[0]), "+f"((d)[1]), "+f"((d)[2]), "+f"((d)[3])       \
        : "r"((a)[0]), "r"((a)[1]), "r"((a)[2]), "r"((a)[3]),          \
          "r"((b)[0]), "r"((b)[1]))

__global__ __launch_bounds__(256, 1)
void main_gemm_tc(const float* __restrict__ enc,
                  const float* __restrict__ Wenc,
                  const float* __restrict__ benc,
                  const float* __restrict__ wfull) {
    extern __shared__ __align__(16) float smem[];
    float* sA[2] = { smem,              smem + AS_FLOATS };
    float* sB[2] = { smem + 2*AS_FLOATS, smem + 2*AS_FLOATS + BS_FLOATS };

    const int tid  = threadIdx.x;
    const int lane = tid & 31;
    const int warp = tid >> 5;
    const int mw   = warp >> 2;     // 0..1  (m block of 64)
    const int nw   = warp & 3;      // 0..3  (n block of 64)
    const int lr   = lane >> 2;     // 0..7
    const int lc   = lane & 3;      // 0..3

    const int rowBase = blockIdx.x * BM;
    const int colBase = blockIdx.y * BN;

    const uint32_t sbase = (uint32_t)__cvta_generic_to_shared(smem);
    const uint32_t sAu[2] = { sbase, sbase + AS_FLOATS*4u };
    const uint32_t sBu[2] = { sbase + 2u*AS_FLOATS*4u,
                              sbase + 2u*AS_FLOATS*4u + BS_FLOATS*4u };

    float acc[4][8][4];
    #pragma unroll
    for (int mi = 0; mi < 4; mi++)
        #pragma unroll
        for (int nj = 0; nj < 8; nj++)
            #pragma unroll
            for (int e = 0; e < 4; e++) acc[mi][nj][e] = 0.0f;

    // ---- async loaders: A tile 128x32, B tile 32x256 (16B chunks) ----
    auto load_stage = [&](int s, int k0) {
        #pragma unroll
        for (int i = 0; i < 4; i++) {               // A: 1024 chunks / 256 thr
            int id = tid + i * 256;
            int m = id >> 3, c = id & 7;
            cp16(sAu[s] + (uint32_t)(m * AS_STRIDE + c * 4) * 4u,
                 enc + (size_t)(rowBase + m) * E_ + k0 + c * 4);
        }
        #pragma unroll
        for (int i = 0; i < 8; i++) {               // B: 2048 chunks / 256 thr
            int id = tid + i * 256;
            int k = id >> 6, c = id & 63;
            cp16(sBu[s] + (uint32_t)(k * BS_STRIDE + c * 4) * 4u,
                 Wenc + (size_t)(k0 + k) * A_ + colBase + c * 4);
        }
        asm volatile("cp.async.commit_group;\n");
    };

    load_stage(0, 0);

    for (int t = 0; t < KTILES; t++) {
        asm volatile("cp.async.wait_group 0;\n");
        __syncthreads();
        if (t + 1 < KTILES) load_stage((t + 1) & 1, (t + 1) * BK);

        const float* A = sA[t & 1];
        const float* Bv = sB[t & 1];

        #pragma unroll
        for (int kk = 0; kk < 4; kk++) {
            const int ko = kk * 8;
            uint32_t a[4][4];
            #pragma unroll
            for (int mi = 0; mi < 4; mi++) {
                const uint32_t* ap = (const uint32_t*)
                    (A + (mw * 64 + mi * 16 + lr) * AS_STRIDE + ko + lc);
                a[mi][0] = ap[0];
                a[mi][1] = ap[8 * AS_STRIDE];
                a[mi][2] = ap[4];
                a[mi][3] = ap[8 * AS_STRIDE + 4];
            }
            uint32_t b[8][2];
            #pragma unroll
            for (int nj = 0; nj < 8; nj++) {
                const uint32_t* bp = (const uint32_t*)
                    (Bv + (size_t)(ko + lc) * BS_STRIDE + nw * 64 + nj * 8 + lr);
                b[nj][0] = bp[0];
                b[nj][1] = bp[4 * BS_STRIDE];
            }
            #pragma unroll
            for (int mi = 0; mi < 4; mi++)
                #pragma unroll
                for (int nj = 0; nj < 8; nj++)
                    MMA_TF32(acc[mi][nj], a[mi], b[nj]);
        }
        // no trailing sync needed: next-iter sync (after wait) protects buffers
    }

    // ---- fused epilogue: relu(att1 + benc + att2) . wfull, per-row sums ----
    __syncthreads();                 // all MMA consumers done; reuse smem
    float* sa2 = smem;               // [2][256] = benc[c] + att2[b, c]
    float* sw  = smem + 512;         // [256]
    const int b0 = rowBase / P_;
    const int boundary = (b0 + 1) * P_ - rowBase;   // local row where batch++

    for (int i = tid; i < 512; i += 256) {
        int bb = b0 + (i >> 8); if (bb > B_ - 1) bb = B_ - 1;
        int c = i & 255;
        sa2[i] = benc[colBase + c] + g_att2[bb * A_ + colBase + c];
    }
    if (tid < 256) sw[tid] = wfull[colBase + tid];
    __syncthreads();

    #pragma unroll
    for (int mi = 0; mi < 4; mi++) {
        #pragma unroll
        for (int h = 0; h < 2; h++) {
            const int rl = mw * 64 + mi * 16 + h * 8 + lr;
            const float* a2p = sa2 + ((rl >= boundary) ? 256 : 0);
            float s = 0.0f;
            #pragma unroll
            for (int nj = 0; nj < 8; nj++) {
                const int cl = nw * 64 + nj * 8 + 2 * lc;
                float v0 = acc[mi][nj][h * 2 + 0] + a2p[cl];
                float v1 = acc[mi][nj][h * 2 + 1] + a2p[cl + 1];
                s = fmaf(fmaxf(v0, 0.0f), sw[cl], s);
                s = fmaf(fmaxf(v1, 0.0f), sw[cl + 1], s);
            }
            s += __shfl_xor_sync(0xFFFFFFFFu, s, 1);
            s += __shfl_xor_sync(0xFFFFFFFFu, s, 2);
            if (lc == 0) atomicAdd(&g_att[rowBase + rl], s);
        }
    }
}

// ---------------------------------------------------------------------------
// Stage 3: softmax over P=196 per batch
// ---------------------------------------------------------------------------
__global__ void softmax_kernel(float* __restrict__ alpha_out) {
    __shared__ float sdata[256];
    const int b = blockIdx.x;
    const int t = threadIdx.x;

    float v = (t < P_) ? g_att[b * P_ + t] : -CUDART_INF_F;
    sdata[t] = v;
    __syncthreads();
    for (int s = 128; s > 0; s >>= 1) {
        if (t < s) sdata[t] = fmaxf(sdata[t], sdata[t + s]);
        __syncthreads();
    }
    float m = sdata[0];
    __syncthreads();

    float e = (t < P_) ? expf(v - m) : 0.0f;
    sdata[t] = e;
    __syncthreads();
    for (int s = 128; s > 0; s >>= 1) {
        if (t < s) sdata[t] += sdata[t + s];
        __syncthreads();
    }
    float inv = 1.0f / sdata[0];
    if (t < P_) alpha_out[b * P_ + t] = e * inv;
}

// ---------------------------------------------------------------------------
// Stage 4: awe[b,e] = sum_p enc[b,p,e] * alpha[b,p]   (HBM-bound)
// ---------------------------------------------------------------------------
__global__ void awe_kernel(const float* __restrict__ enc,
                           const float* __restrict__ alpha,
                           float* __restrict__ awe) {
    __shared__ float sa[P_];
    const int b = blockIdx.y;
    const int e = blockIdx.x * 256 + threadIdx.x;
    for (int i = threadIdx.x; i < P_; i += 256)
        sa[i] = alpha[b * P_ + i];
    __syncthreads();

    const float* base = enc + (size_t)b * P_ * E_ + e;
    float acc = 0.0f;
    #pragma unroll 4
    for (int p = 0; p < P_; p++)
        acc = fmaf(base[(size_t)p * E_], sa[p], acc);
    awe[b * E_ + e] = acc;
}

// ---------------------------------------------------------------------------
extern "C" void kernel_launch(void* const* d_in, const int* in_sizes, int n_in,
                              void* d_out, int out_size) {
    const float* enc   = (const float*)d_in[0];
    const float* dh    = (const float*)d_in[1];
    const float* Wenc  = (const float*)d_in[2];
    const float* benc  = (const float*)d_in[3];
    const float* Wdec  = (const float*)d_in[4];
    const float* bdec  = (const float*)d_in[5];
    const float* wfull = (const float*)d_in[6];
    // d_in[7] = b_full: softmax-invariant, dropped.

    float* awe   = (float*)d_out;
    float* alpha = (float*)d_out + (size_t)B_ * E_;

    static int smem_set = 0;
    if (!smem_set) {
        cudaFuncSetAttribute(main_gemm_tc,
                             cudaFuncAttributeMaxDynamicSharedMemorySize,
                             SMEM_FLOATS * 4);
        smem_set = 1;
    }

    init_att_kernel<<<(M_ + 255) / 256, 256>>>();
    att2_kernel<<<dim3(A_ / 128, B_ / 16), 256>>>(dh, Wdec, bdec);
    main_gemm_tc<<<dim3(M_ / BM, A_ / BN), 256, SMEM_FLOATS * 4>>>(enc, Wenc, benc, wfull);
    softmax_kernel<<<B_, 256>>>(alpha);
    awe_kernel<<<dim3(E_ / 256, B_), 256>>>(enc, alpha, awe);
}

// round 5
// speedup vs baseline: 4.6407x; 1.5424x over previous
#include <cuda_runtime.h>
#include <cuda_fp16.h>
#include <math_constants.h>
#include <cstdint>

#define B_ 256
#define P_ 196
#define E_ 2048
#define D_ 512
#define A_ 512
#define M_ (B_*P_)   // 50176

// Scratch: att2 [B,A], partial logits [2][M], fp16-transposed Wenc [A,E]
__device__ float  g_att2[B_*A_];
__device__ float  g_attp[2*M_];
__device__ __half g_WhT[A_*E_];

// ---------------------------------------------------------------------------
__device__ __forceinline__ uint32_t smem_u32(const void* p) {
    uint32_t a;
    asm("{ .reg .u64 t; cvta.to.shared.u64 t, %1; cvt.u32.u64 %0, t; }"
        : "=r"(a) : "l"(p));
    return a;
}
__device__ __forceinline__ void cp16(uint32_t saddr, const void* gaddr) {
    asm volatile("cp.async.cg.shared.global [%0], [%1], 16;\n"
                 :: "r"(saddr), "l"(gaddr));
}
__device__ __forceinline__ void ldsm4(uint32_t* r, uint32_t addr) {
    asm volatile("ldmatrix.sync.aligned.m8n8.x4.shared.b16 {%0,%1,%2,%3}, [%4];"
                 : "=r"(r[0]), "=r"(r[1]), "=r"(r[2]), "=r"(r[3]) : "r"(addr));
}
#define MMA_F16(d, a, b)                                               \
    asm volatile(                                                      \
        "mma.sync.aligned.m16n8k16.row.col.f32.f16.f16.f32 "           \
        "{%0,%1,%2,%3}, {%4,%5,%6,%7}, {%8,%9}, {%0,%1,%2,%3};\n"      \
        : "+f"((d)[0]), "+f"((d)[1]), "+f"((d)[2]), "+f"((d)[3])       \
        : "r"((a)[0]), "r"((a)[1]), "r"((a)[2]), "r"((a)[3]),          \
          "r"((b)[0]), "r"((b)[1]))

// ---------------------------------------------------------------------------
// Stage 0: transpose + convert Wenc [E,A] f32 -> g_WhT [A,E] fp16
// ---------------------------------------------------------------------------
__global__ void transpose_kernel(const float* __restrict__ W) {
    __shared__ float tile[32][33];
    const int k0 = blockIdx.x * 32, n0 = blockIdx.y * 32;
    for (int i = threadIdx.y; i < 32; i += 8)
        tile[i][threadIdx.x] = W[(size_t)(k0 + i) * A_ + n0 + threadIdx.x];
    __syncthreads();
    for (int i = threadIdx.y; i < 32; i += 8)
        g_WhT[(size_t)(n0 + i) * E_ + k0 + threadIdx.x] =
            __float2half_rn(tile[threadIdx.x][i]);
}

// ---------------------------------------------------------------------------
// Stage 1: att2[b,a] = decoder_hidden[b,:] @ W_dec[:,a] + b_dec[a]
// ---------------------------------------------------------------------------
__global__ void att2_kernel(const float* __restrict__ dh,
                            const float* __restrict__ Wdec,
                            const float* __restrict__ bdec) {
    __shared__ float sdh[16][D_];
    const int colBase = blockIdx.x * 128;
    const int bBase   = blockIdx.y * 16;
    const int t = threadIdx.x;

    for (int i = t; i < 16 * D_; i += 256) {
        int bb = i / D_, k = i % D_;
        sdh[bb][k] = dh[(bBase + bb) * D_ + k];
    }
    __syncthreads();

    const int col   = colBase + (t & 127);
    const int bhalf = t >> 7;
    float acc[8];
    #pragma unroll
    for (int i = 0; i < 8; i++) acc[i] = 0.0f;

    for (int k = 0; k < D_; k++) {
        float w = Wdec[k * A_ + col];
        #pragma unroll
        for (int i = 0; i < 8; i++)
            acc[i] = fmaf(sdh[bhalf * 8 + i][k], w, acc[i]);
    }
    float bd = bdec[col];
    #pragma unroll
    for (int i = 0; i < 8; i++)
        g_att2[(bBase + bhalf * 8 + i) * A_ + col] = acc[i] + bd;
}

// ---------------------------------------------------------------------------
// Stage 2: fp16 mma.sync GEMM + fused epilogue.
//   BM=128, BN=256, BK=32 (2 x k16), 512 threads (16 warps, tile 32x64)
//   A: enc f32 -> fp16 in load path. B: g_WhT via cp.async.
//   Epilogue: att_part[r] = sum_c relu(att1+benc+att2)*wfull  (per N-half)
// ---------------------------------------------------------------------------
#define AS 40                        // smem row stride in halves (80 B, conflict-free)
#define KT (E_/32)                   // 64 stages
#define SM_A0 0
#define SM_A1 10240
#define SM_B0 20480
#define SM_B1 40960
#define SM_TOTAL 61440

__global__ __launch_bounds__(512, 1)
void main_gemm_h(const float* __restrict__ enc,
                 const float* __restrict__ benc,
                 const float* __restrict__ wfull) {
    extern __shared__ __align__(128) char smem[];
    const uint32_t sb = smem_u32(smem);
    const int tid  = threadIdx.x;
    const int lane = tid & 31;
    const int warp = tid >> 5;
    const int mw   = warp >> 2;          // 0..3  (m block of 32)
    const int nw   = warp & 3;           // 0..3  (n block of 64)
    const int rowBase = blockIdx.x * 128;
    const int colBase = blockIdx.y * 256;
    const int nhalf   = blockIdx.y;

    const uint32_t aBuf[2] = { sb + SM_A0, sb + SM_A1 };
    const uint32_t bBuf[2] = { sb + SM_B0, sb + SM_B1 };

    // ldmatrix per-thread address offsets
    const uint32_t aOff = (uint32_t)((mw * 32 + (lane & 15)) * AS * 2)
                        + (uint32_t)((lane >> 4) * 16);
    const int bRow = nw * 64 + (lane & 7) + ((lane >> 4) & 1) * 8;
    const uint32_t bOff = (uint32_t)(bRow * AS * 2)
                        + (uint32_t)(((lane >> 3) & 1) * 16);

    // A loader coords: thread -> (m row, 8-float chunk)
    const int am = tid >> 2;
    const int ac = tid & 3;
    const float* aG = enc + (size_t)(rowBase + am) * E_ + ac * 8;
    const uint32_t aSt = (uint32_t)(am * AS * 2 + ac * 16);

    // B loader coords: 1024 chunks of 16B / 512 threads = 2 each
    const __half* bG0 = g_WhT + (size_t)(colBase + (tid >> 2)) * E_ + (tid & 3) * 8;
    const __half* bG1 = g_WhT + (size_t)(colBase + ((tid + 512) >> 2)) * E_ + (tid & 3) * 8;
    const uint32_t bSt0 = (uint32_t)((tid >> 2) * AS * 2 + (tid & 3) * 16);
    const uint32_t bSt1 = (uint32_t)(((tid + 512) >> 2) * AS * 2 + (tid & 3) * 16);

    auto ldgA = [&](int k0) -> uint4 {
        float4 f0 = *(const float4*)(aG + k0);
        float4 f1 = *(const float4*)(aG + k0 + 4);
        __half2 h0 = __floats2half2_rn(f0.x, f0.y);
        __half2 h1 = __floats2half2_rn(f0.z, f0.w);
        __half2 h2 = __floats2half2_rn(f1.x, f1.y);
        __half2 h3 = __floats2half2_rn(f1.z, f1.w);
        uint4 u;
        u.x = *(uint32_t*)&h0; u.y = *(uint32_t*)&h1;
        u.z = *(uint32_t*)&h2; u.w = *(uint32_t*)&h3;
        return u;
    };
    auto cpB = [&](int s, int k0) {
        cp16(bBuf[s] + bSt0, bG0 + k0);
        cp16(bBuf[s] + bSt1, bG1 + k0);
        asm volatile("cp.async.commit_group;\n" ::: "memory");
    };

    float acc[2][8][4];
    #pragma unroll
    for (int mi = 0; mi < 2; mi++)
        #pragma unroll
        for (int nj = 0; nj < 8; nj++)
            #pragma unroll
            for (int e = 0; e < 4; e++) acc[mi][nj][e] = 0.0f;

    // prologue: stage 0
    {
        uint4 a0 = ldgA(0);
        *(uint4*)(smem + SM_A0 + aSt) = a0;
        cpB(0, 0);
    }

    for (int t = 0; t < KT; t++) {
        const int s = t & 1;
        asm volatile("cp.async.wait_group 0;\n" ::: "memory");
        __syncthreads();

        uint4 aNext;
        if (t + 1 < KT) {
            cpB(s ^ 1, (t + 1) * 32);
            aNext = ldgA((t + 1) * 32);
        }

        const uint32_t aB = aBuf[s], bB = bBuf[s];
        #pragma unroll
        for (int kk = 0; kk < 2; kk++) {
            uint32_t af[2][4];
            ldsm4(af[0], aB + aOff + kk * 32);
            ldsm4(af[1], aB + aOff + 1280 + kk * 32);   // mi=1: +16 rows*80B
            uint32_t bf[8][2];
            #pragma unroll
            for (int p = 0; p < 4; p++) {
                uint32_t r4[4];
                ldsm4(r4, bB + bOff + p * 1280 + kk * 32);  // pair: +16 rows*80B
                bf[2*p][0]   = r4[0]; bf[2*p][1]   = r4[1];
                bf[2*p+1][0] = r4[2]; bf[2*p+1][1] = r4[3];
            }
            #pragma unroll
            for (int mi = 0; mi < 2; mi++)
                #pragma unroll
                for (int nj = 0; nj < 8; nj++)
                    MMA_F16(acc[mi][nj], af[mi], bf[nj]);
        }

        if (t + 1 < KT)
            *(uint4*)(smem + (SM_A0 + (s ^ 1) * 10240) + aSt) = aNext;
    }

    // ---- fused epilogue ----
    __syncthreads();                 // reuse smem
    float* sa2 = (float*)smem;       // [2][256]: benc + att2 for 2 local batches
    float* sw  = (float*)smem + 512; // [256]
    float* red = (float*)smem + 768; // [128][5]
    const int b0 = rowBase / P_;
    const int boundary = (b0 + 1) * P_ - rowBase;

    for (int i = tid; i < 512; i += 512) {
        int bb = b0 + (i >> 8); if (bb > B_ - 1) bb = B_ - 1;
        int c = i & 255;
        sa2[i] = benc[colBase + c] + g_att2[bb * A_ + colBase + c];
    }
    {   // second half of sa2 + sw (512 threads cover 512+256 via two strides)
        int i = tid + 512;
        if (i < 1024) { /* unreachable: loop above strided 512 covers 0..511 only */ }
    }
    if (tid < 256) {
        int bb = b0 + 1; if (bb > B_ - 1) bb = B_ - 1;
        sa2[256 + tid] = 0.0f; // placeholder overwritten below if needed
        sa2[256 + tid] = benc[colBase + tid] + g_att2[bb * A_ + colBase + tid];
        // note: sa2[0..255] written above for i<256? fix: write both halves here
    }
    if (tid >= 256 && tid < 512) {
        int c = tid - 256;
        sa2[c] = benc[colBase + c] + g_att2[b0 * A_ + colBase + c];
    }
    if (tid < 256) sw[tid] = wfull[colBase + tid];
    __syncthreads();

    const int c0l = nw * 64 + 2 * (lane & 3);
    #pragma unroll
    for (int mi = 0; mi < 2; mi++) {
        #pragma unroll
        for (int h = 0; h < 2; h++) {
            const int rl = mw * 32 + mi * 16 + h * 8 + (lane >> 2);
            const float* a2p = sa2 + ((rl >= boundary) ? 256 : 0);
            float s = 0.0f;
            #pragma unroll
            for (int nj = 0; nj < 8; nj++) {
                const int c = c0l + nj * 8;
                float v0 = acc[mi][nj][h * 2 + 0] + a2p[c];
                float v1 = acc[mi][nj][h * 2 + 1] + a2p[c + 1];
                s = fmaf(fmaxf(v0, 0.0f), sw[c], s);
                s = fmaf(fmaxf(v1, 0.0f), sw[c + 1], s);
            }
            s += __shfl_xor_sync(0xFFFFFFFFu, s, 1);
            s += __shfl_xor_sync(0xFFFFFFFFu, s, 2);
            if ((lane & 3) == 0) red[rl * 5 + nw] = s;
        }
    }
    __syncthreads();
    if (tid < 128) {
        float s = red[tid * 5 + 0] + red[tid * 5 + 1]
                + red[tid * 5 + 2] + red[tid * 5 + 3];
        g_attp[nhalf * M_ + rowBase + tid] = s;
    }
}

// ---------------------------------------------------------------------------
// Stage 3: softmax over P=196 per batch (sums the two N-half partials)
// ---------------------------------------------------------------------------
__global__ void softmax_kernel(float* __restrict__ alpha_out) {
    __shared__ float sdata[256];
    const int b = blockIdx.x;
    const int t = threadIdx.x;

    float v = -CUDART_INF_F;
    if (t < P_) {
        int r = b * P_ + t;
        v = g_attp[r] + g_attp[M_ + r];
    }
    sdata[t] = v;
    __syncthreads();
    for (int s = 128; s > 0; s >>= 1) {
        if (t < s) sdata[t] = fmaxf(sdata[t], sdata[t + s]);
        __syncthreads();
    }
    float m = sdata[0];
    __syncthreads();

    float e = (t < P_) ? expf(v - m) : 0.0f;
    sdata[t] = e;
    __syncthreads();
    for (int s = 128; s > 0; s >>= 1) {
        if (t < s) sdata[t] += sdata[t + s];
        __syncthreads();
    }
    float inv = 1.0f / sdata[0];
    if (t < P_) alpha_out[b * P_ + t] = e * inv;
}

// ---------------------------------------------------------------------------
// Stage 4: awe[b,e] = sum_p enc[b,p,e] * alpha[b,p]
// ---------------------------------------------------------------------------
__global__ void awe_kernel(const float* __restrict__ enc,
                           const float* __restrict__ alpha,
                           float* __restrict__ awe) {
    __shared__ float sa[P_];
    const int b = blockIdx.y;
    const int e = blockIdx.x * 256 + threadIdx.x;
    for (int i = threadIdx.x; i < P_; i += 256)
        sa[i] = alpha[b * P_ + i];
    __syncthreads();

    const float* base = enc + (size_t)b * P_ * E_ + e;
    float acc = 0.0f;
    #pragma unroll 4
    for (int p = 0; p < P_; p++)
        acc = fmaf(base[(size_t)p * E_], sa[p], acc);
    awe[b * E_ + e] = acc;
}

// ---------------------------------------------------------------------------
extern "C" void kernel_launch(void* const* d_in, const int* in_sizes, int n_in,
                              void* d_out, int out_size) {
    const float* enc   = (const float*)d_in[0];
    const float* dh    = (const float*)d_in[1];
    const float* Wenc  = (const float*)d_in[2];
    const float* benc  = (const float*)d_in[3];
    const float* Wdec  = (const float*)d_in[4];
    const float* bdec  = (const float*)d_in[5];
    const float* wfull = (const float*)d_in[6];
    // d_in[7] = b_full: softmax-invariant, dropped.

    float* awe   = (float*)d_out;
    float* alpha = (float*)d_out + (size_t)B_ * E_;

    static int smem_set = 0;
    if (!smem_set) {
        cudaFuncSetAttribute(main_gemm_h,
                             cudaFuncAttributeMaxDynamicSharedMemorySize,
                             SM_TOTAL);
        smem_set = 1;
    }

    transpose_kernel<<<dim3(E_ / 32, A_ / 32), dim3(32, 8)>>>(Wenc);
    att2_kernel<<<dim3(A_ / 128, B_ / 16), 256>>>(dh, Wdec, bdec);
    main_gemm_h<<<dim3(M_ / 128, 2), 512, SM_TOTAL>>>(enc, benc, wfull);
    softmax_kernel<<<B_, 256>>>(alpha);
    awe_kernel<<<dim3(E_ / 256, B_), 256>>>(enc, alpha, awe);
}